// round 6
// baseline (speedup 1.0000x reference)
#include <cuda_runtime.h>
#include <math.h>

// Problem constants (fixed by setup_inputs): B=4, N=2048, D=64
#define BB 4
#define NN 2048
#define DD 64
#define TILE_N 16
#define MC 128
#define MSTRIDE 68   // floats; 16B-aligned rows, conflict-free for LDS.128

// ---------------- device scratch (static; no allocations) ----------------
__device__ float g_nf[BB*NN*DD];          // normalized features (2 MB)
__device__ float g_fnorm[BB*NN];
__device__ float g_csq[BB*NN];
__device__ float g_psq[BB*NN];
__device__ float g_c3[BB*NN*3];
__device__ float g_fs[BB*NN*NN];          // feature gram (64 MB)
__device__ float g_wl[BB*NN];             // within-loss per row (3 taus combined)
__device__ float g_negsum[BB*NN];
__device__ float g_samnll[BB*NN];
__device__ float g_samvalid[BB*NN];

__device__ __forceinline__ float wsum(float v) {
    #pragma unroll
    for (int o = 16; o; o >>= 1) v += __shfl_xor_sync(0xffffffffu, v, o);
    return v;
}

// ---------------- K0: per-point prep ----------------
__global__ void prep_kernel(const float* __restrict__ feat,
                            const float* __restrict__ flow,
                            const float* __restrict__ points,
                            const int*   __restrict__ colors)
{
    int gw   = (blockIdx.x * blockDim.x + threadIdx.x) >> 5;  // one warp per point
    int lane = threadIdx.x & 31;
    if (gw >= BB * NN) return;

    const float* f = feat + gw * DD;
    float v0 = f[lane], v1 = f[lane + 32];
    float ss = wsum(v0 * v0 + v1 * v1);
    float inv = 1.0f / (sqrtf(ss) + 1e-7f);
    g_nf[gw * DD + lane]      = v0 * inv;
    g_nf[gw * DD + lane + 32] = v1 * inv;

    if (lane == 0) {
        float fx = flow[gw*3+0], fy = flow[gw*3+1], fz = flow[gw*3+2];
        g_fnorm[gw] = sqrtf(fx*fx + fy*fy + fz*fz);
        float c0 = colors[gw*3+0] * (1.0f/255.0f);
        float c1 = colors[gw*3+1] * (1.0f/255.0f);
        float c2 = colors[gw*3+2] * (1.0f/255.0f);
        g_c3[gw*3+0] = c0; g_c3[gw*3+1] = c1; g_c3[gw*3+2] = c2;
        g_csq[gw] = c0*c0 + c1*c1 + c2*c2;
        float p0 = points[gw*3+0], p1 = points[gw*3+1], p2 = points[gw*3+2];
        g_psq[gw] = p0*p0 + p1*p1 + p2*p2;
    }
}

// ---------------- K1: main pairwise pass ----------------
// Block: 256 threads = 8 warps. Warp w owns rows {w, w+8} of a 16-row tile.
// Lane l owns m = l + 32*j (j = 0..3) within each 128-wide m-chunk.
__global__ __launch_bounds__(256) void pair_kernel(
        const float* __restrict__ flow,
        const float* __restrict__ points,
        const int*   __restrict__ sam,
        const unsigned char* __restrict__ mask)
{
    __shared__ float s_nfm[MC * MSTRIDE];
    __shared__ float s_nfr[TILE_N * DD];
    __shared__ float s_fl[MC*3], s_fn[MC], s_cc[MC*3], s_cs[MC];
    __shared__ float s_pp[MC*3], s_ps[MC], s_mk[MC];
    __shared__ int   s_sm[MC];

    const int b   = blockIdx.y;
    const int n0  = blockIdx.x * TILE_N;
    const int tid = threadIdx.x;
    const int warp = tid >> 5, lane = tid & 31;
    const int r0 = warp, r1 = warp + 8;
    const int gi0 = b*NN + n0 + r0;
    const int gi1 = b*NN + n0 + r1;

    // row tile: 16*64 floats = 256 float4, one per thread
    {
        const float4* src = (const float4*)&g_nf[(b*NN + n0) * DD];
        ((float4*)s_nfr)[tid] = src[tid];
    }

    // row-side data (uniform within warp -> broadcast loads)
    float fl0x = flow[gi0*3+0], fl0y = flow[gi0*3+1], fl0z = flow[gi0*3+2];
    float fl1x = flow[gi1*3+0], fl1y = flow[gi1*3+1], fl1z = flow[gi1*3+2];
    float fn0 = g_fnorm[gi0], fn1 = g_fnorm[gi1];
    float c0x = g_c3[gi0*3+0], c0y = g_c3[gi0*3+1], c0z = g_c3[gi0*3+2];
    float c1x = g_c3[gi1*3+0], c1y = g_c3[gi1*3+1], c1z = g_c3[gi1*3+2];
    float cs0 = g_csq[gi0], cs1 = g_csq[gi1];
    float p0x = points[gi0*3+0], p0y = points[gi0*3+1], p0z = points[gi0*3+2];
    float p1x = points[gi1*3+0], p1y = points[gi1*3+1], p1z = points[gi1*3+2];
    float ps0 = g_psq[gi0], ps1 = g_psq[gi1];
    int   sm0 = sam[gi0], sm1 = sam[gi1];
    float mk0 = mask[gi0] ? 1.0f : 0.0f;
    float mk1 = mask[gi1] ? 1.0f : 0.0f;

    // accumulators: s_plus / s_minus for (flow, color, prox), plus neg-exp sum
    float spA0=0.f,spB0=0.f,spC0=0.f, snA0=0.f,snB0=0.f,snC0=0.f, neg0=0.f;
    float spA1=0.f,spB1=0.f,spC1=0.f, snA1=0.f,snB1=0.f,snC1=0.f, neg1=0.f;

    for (int m0 = 0; m0 < NN; m0 += MC) {
        __syncthreads();
        // 128*64 floats = 2048 float4 -> 8 per thread
        {
            const float4* src = (const float4*)&g_nf[(b*NN + m0) * DD];
            #pragma unroll
            for (int k = 0; k < 8; k++) {
                int idx = tid + 256*k;          // float4 index; 16 per m-row
                int m = idx >> 4, d4 = idx & 15;
                *(float4*)&s_nfm[m * MSTRIDE + 4*d4] = src[idx];
            }
        }
        if (tid < MC) {
            int gm = b*NN + m0 + tid;
            s_fn[tid] = g_fnorm[gm]; s_cs[tid] = g_csq[gm]; s_ps[tid] = g_psq[gm];
            s_mk[tid] = mask[gm] ? 1.0f : 0.0f;
            s_sm[tid] = sam[gm];
            s_fl[tid*3+0] = flow[gm*3+0]; s_fl[tid*3+1] = flow[gm*3+1]; s_fl[tid*3+2] = flow[gm*3+2];
            s_cc[tid*3+0] = g_c3[gm*3+0]; s_cc[tid*3+1] = g_c3[gm*3+1]; s_cc[tid*3+2] = g_c3[gm*3+2];
            s_pp[tid*3+0] = points[gm*3+0]; s_pp[tid*3+1] = points[gm*3+1]; s_pp[tid*3+2] = points[gm*3+2];
        }
        __syncthreads();

        // feature gram: 2 rows x 4 m per thread, float4 (LDS.128) inner loop
        float fs0[4] = {0.f,0.f,0.f,0.f};
        float fs1[4] = {0.f,0.f,0.f,0.f};
        const float4* a0v = (const float4*)&s_nfr[r0*DD];
        const float4* a1v = (const float4*)&s_nfr[r1*DD];
        #pragma unroll
        for (int d4 = 0; d4 < DD/4; d4++) {
            float4 a0 = a0v[d4];
            float4 a1 = a1v[d4];
            #pragma unroll
            for (int j = 0; j < 4; j++) {
                float4 bm = *(const float4*)&s_nfm[(lane + 32*j) * MSTRIDE + 4*d4];
                fs0[j] = fmaf(a0.x, bm.x, fs0[j]);
                fs0[j] = fmaf(a0.y, bm.y, fs0[j]);
                fs0[j] = fmaf(a0.z, bm.z, fs0[j]);
                fs0[j] = fmaf(a0.w, bm.w, fs0[j]);
                fs1[j] = fmaf(a1.x, bm.x, fs1[j]);
                fs1[j] = fmaf(a1.y, bm.y, fs1[j]);
                fs1[j] = fmaf(a1.z, bm.z, fs1[j]);
                fs1[j] = fmaf(a1.w, bm.w, fs1[j]);
            }
        }

        #pragma unroll
        for (int j = 0; j < 4; j++) {
            int   m   = lane + 32*j;
            float mm  = s_mk[m];
            float fnm = s_fn[m];
            float flx = s_fl[m*3+0], fly = s_fl[m*3+1], flz = s_fl[m*3+2];
            float ccx = s_cc[m*3+0], ccy = s_cc[m*3+1], ccz = s_cc[m*3+2];
            float csm = s_cs[m];
            float ppx = s_pp[m*3+0], ppy = s_pp[m*3+1], ppz = s_pp[m*3+2];
            float psm = s_ps[m];
            int   smm = s_sm[m];

            // ---- row 0 ----
            {
                float f  = fs0[j];
                float mp = mk0 * mm;
                float fdot  = fl0x*flx + fl0y*fly + fl0z*flz;
                float sflow = __fdividef(fdot, fn0*fnm + 1e-8f) * mp;
                float cdot  = c0x*ccx + c0y*ccy + c0z*ccz;
                float cd    = sqrtf(fmaxf(cs0 + csm - 2.0f*cdot, 0.0f));
                float scol  = (1.0f - cd * 0.5773502691896258f) * mp;
                float pdot  = p0x*ppx + p0y*ppy + p0z*ppz;
                float pd    = sqrtf(fmaxf(ps0 + psm - 2.0f*pdot, 0.0f));
                float sprox = __expf(-50.0f * pd) * mp;

                // issue all independent MUFU exps up front to overlap latency
                float ef = __expf(f);
                float en = __expf(-f);
                float eA = __expf(5.0f*(0.8f - sflow));
                float eB = __expf(5.0f*(0.7f - scol));
                float eC = __expf(5.0f*(0.5f - sprox));

                float gp, ep;
                gp = __fdividef(1.0f, 1.0f + eA);
                ep = __expf(f * gp); spA0 += ep; snA0 += ep * en;
                gp = __fdividef(1.0f, 1.0f + eB);
                ep = __expf(f * gp); spB0 += ep; snB0 += ep * en;
                gp = __fdividef(1.0f, 1.0f + eC);
                ep = __expf(f * gp); spC0 += ep; snC0 += ep * en;
                neg0 += (smm != sm0) ? ef : 0.0f;     // branchless select
                g_fs[(size_t)gi0 * NN + m0 + m] = f;
            }
            // ---- row 1 ----
            {
                float f  = fs1[j];
                float mp = mk1 * mm;
                float fdot  = fl1x*flx + fl1y*fly + fl1z*flz;
                float sflow = __fdividef(fdot, fn1*fnm + 1e-8f) * mp;
                float cdot  = c1x*ccx + c1y*ccy + c1z*ccz;
                float cd    = sqrtf(fmaxf(cs1 + csm - 2.0f*cdot, 0.0f));
                float scol  = (1.0f - cd * 0.5773502691896258f) * mp;
                float pdot  = p1x*ppx + p1y*ppy + p1z*ppz;
                float pd    = sqrtf(fmaxf(ps1 + psm - 2.0f*pdot, 0.0f));
                float sprox = __expf(-50.0f * pd) * mp;

                float ef = __expf(f);
                float en = __expf(-f);
                float eA = __expf(5.0f*(0.8f - sflow));
                float eB = __expf(5.0f*(0.7f - scol));
                float eC = __expf(5.0f*(0.5f - sprox));

                float gp, ep;
                gp = __fdividef(1.0f, 1.0f + eA);
                ep = __expf(f * gp); spA1 += ep; snA1 += ep * en;
                gp = __fdividef(1.0f, 1.0f + eB);
                ep = __expf(f * gp); spB1 += ep; snB1 += ep * en;
                gp = __fdividef(1.0f, 1.0f + eC);
                ep = __expf(f * gp); spC1 += ep; snC1 += ep * en;
                neg1 += (smm != sm1) ? ef : 0.0f;
                g_fs[(size_t)gi1 * NN + m0 + m] = f;
            }
        }
    }

    // warp reductions (all lanes of this warp worked on the same 2 rows)
    spA0 = wsum(spA0); spB0 = wsum(spB0); spC0 = wsum(spC0);
    snA0 = wsum(snA0); snB0 = wsum(snB0); snC0 = wsum(snC0); neg0 = wsum(neg0);
    spA1 = wsum(spA1); spB1 = wsum(spB1); spC1 = wsum(spC1);
    snA1 = wsum(snA1); snB1 = wsum(snB1); snC1 = wsum(snC1); neg1 = wsum(neg1);

    if (lane == 0) {
        g_wl[gi0] = mk0 * (log1pf(spA0)+log1pf(snA0)+log1pf(spB0)+log1pf(snB0)+log1pf(spC0)+log1pf(snC0));
        g_negsum[gi0] = neg0;
        g_wl[gi1] = mk1 * (log1pf(spA1)+log1pf(snA1)+log1pf(spB1)+log1pf(snB1)+log1pf(spC1)+log1pf(snC1));
        g_negsum[gi1] = neg1;
    }
}

// ---------------- K2: SAM second pass (pos-pair nll) ----------------
__global__ void sam_kernel(const int* __restrict__ sam)
{
    int row  = (blockIdx.x * blockDim.x + threadIdx.x) >> 5;  // one warp per row
    int lane = threadIdx.x & 31;
    if (row >= BB * NN) return;

    int b  = row / NN;
    int sn = sam[row];
    float ns = g_negsum[row];
    const float* fsrow = g_fs + (size_t)row * NN;
    const int*   samb  = sam + b * NN;

    float acc = 0.f, cnt = 0.f;
    for (int m = lane; m < NN; m += 32) {
        if (samb[m] == sn) {
            float f = fsrow[m];
            // log(exp(f)+ns) - f == log1p(ns*exp(-f))
            acc += log1pf(ns * __expf(-f));
            cnt += 1.0f;
        }
    }
    acc = wsum(acc);
    cnt = wsum(cnt);
    if (lane == 0) {
        float valid = (cnt > 0.f) ? 1.0f : 0.0f;
        g_samnll[row]   = valid * acc * __fdividef(1.0f, fmaxf(cnt, 1e-6f));
        g_samvalid[row] = valid;
    }
}

// ---------------- K3: final reduction to scalar ----------------
__global__ void final_kernel(const unsigned char* __restrict__ mask, float* __restrict__ out)
{
    __shared__ float red[32];
    int tid = threadIdx.x, lane = tid & 31, w = tid >> 5;

    float total = 0.0f;
    for (int b = 0; b < BB; b++) {
        float wl = 0.f, mk = 0.f, sn = 0.f, sv = 0.f;
        for (int n = tid; n < NN; n += 256) {
            int gi = b*NN + n;
            wl += g_wl[gi];
            mk += mask[gi] ? 1.0f : 0.0f;
            sn += g_samnll[gi];
            sv += g_samvalid[gi];
        }
        // reduce 4 quantities across the block
        wl = wsum(wl); mk = wsum(mk); sn = wsum(sn); sv = wsum(sv);
        if (lane == 0) { red[w] = wl; red[w+8] = mk; red[w+16] = sn; red[w+24] = sv; }
        __syncthreads();
        if (tid == 0) {
            float WL=0.f, MK=0.f, SN=0.f, SV=0.f;
            #pragma unroll
            for (int i = 0; i < 8; i++) { WL += red[i]; MK += red[i+8]; SN += red[i+16]; SV += red[i+24]; }
            // within losses already return negative mean -> contribute -WL/MK; sam adds +SN/max(SV,1e-6)
            total += -WL / MK + SN / fmaxf(SV, 1e-6f);
        }
        __syncthreads();
    }
    if (tid == 0) out[0] = total / (float)BB;
}

// ---------------- launch ----------------
extern "C" void kernel_launch(void* const* d_in, const int* in_sizes, int n_in,
                              void* d_out, int out_size)
{
    const float* feat   = (const float*)d_in[0];
    const float* flow   = (const float*)d_in[1];
    const float* points = (const float*)d_in[2];
    const int*   colors = (const int*)d_in[3];
    const int*   sam    = (const int*)d_in[4];
    const unsigned char* mask = (const unsigned char*)d_in[5];
    float* out = (float*)d_out;

    prep_kernel<<<(BB*NN)/8, 256>>>(feat, flow, points, colors);
    dim3 g1(NN / TILE_N, BB);
    pair_kernel<<<g1, 256>>>(flow, points, sam, mask);
    sam_kernel<<<(BB*NN)/8, 256>>>(sam);
    final_kernel<<<1, 256>>>(mask, out);
}